// round 17
// baseline (speedup 1.0000x reference)
#include <cuda_runtime.h>
#include <cuda_bf16.h>
#include <stdint.h>
#include <math.h>

// ---------------- model dims ----------------
#define B_ 4
#define L_ 1024
#define D_IN 128
#define D_MODEL 512
#define N_LAYERS 2
#define N_CLASSES 3
#define D_INNER 1024
#define D_STATE 64
#define D_CONV 2
#define DT_RANK 32
#define ML (B_ * L_)

// ---------------- scratch (device globals; no allocation) ----------------
__device__ float g_h[ML * D_MODEL];
__device__ float g_h2[ML * D_MODEL];
__device__ float g_xz[ML * 2 * D_INNER];
__device__ float g_xc[ML * D_INNER];
__device__ float g_dbc[ML * 160];
__device__ float g_y[ML * D_INNER];
__device__ float g_xcT[ML * D_INNER];   // [b][d][t]
__device__ float g_yT[ML * D_INNER];    // [b][d][t]

__device__ __forceinline__ float softplus_f(float v) {
    return (v > 20.f) ? v : log1pf(__expf(v));
}
__device__ __forceinline__ void split2(float e0, float e1, unsigned int& hi, unsigned int& lo) {
    __nv_bfloat162 h = __floats2bfloat162_rn(e0, e1);
    float r0 = e0 - __bfloat162float(h.x);
    float r1 = e1 - __bfloat162float(h.y);
    __nv_bfloat162 l = __floats2bfloat162_rn(r0, r1);
    hi = *reinterpret_cast<unsigned int*>(&h);
    lo = *reinterpret_cast<unsigned int*>(&l);
}
__device__ __forceinline__ void mma_bf16(float* c, const unsigned int* a, const unsigned int* b) {
    asm volatile(
        "mma.sync.aligned.m16n8k16.row.col.f32.bf16.bf16.f32 "
        "{%0,%1,%2,%3}, {%4,%5,%6,%7}, {%8,%9}, {%0,%1,%2,%3};\n"
        : "+f"(c[0]), "+f"(c[1]), "+f"(c[2]), "+f"(c[3])
        : "r"(a[0]), "r"(a[1]), "r"(a[2]), "r"(a[3]),
          "r"(b[0]), "r"(b[1]));
}

// ---------------- split-bf16 (3-term) GEMM (proven R14) ----------------
// C = (A [+A2])(M,K;lda) @ W(N,K;wlda)^T for K-chunk blockIdx.z.
// act: 0 plain (+bias[n] if bias), 3 = atomicAdd, 4 = slice store (z 0->C, 1->C2).
#define SKW 20

template<int TAG>
__global__ __launch_bounds__(256, 2)
void gemm3b(const float* __restrict__ A, const float* __restrict__ A2,
            const float* __restrict__ W,
            const float* __restrict__ bias, float* __restrict__ C,
            float* __restrict__ C2,
            int M, int N, int K, int lda, int wlda, int act)
{
    __shared__ unsigned int SH[2][4][128][SKW];

    const int tid = threadIdx.x;
    const int lane = tid & 31, w = tid >> 5;
    const int g = lane >> 2, l4 = lane & 3;
    const int wm = (w >> 2) * 64, wn = (w & 3) * 32;
    const int m0 = blockIdx.y * 128, n0 = blockIdx.x * 128;
    const int koff = blockIdx.z * K;

    const int lrow = tid >> 1;
    const int lcolf = (tid & 1) * 16;
    const int p0 = lcolf >> 1;
    const float* Ag = A + (long)(m0 + lrow) * lda + lcolf + koff;
    const float* Ag2 = A2 ? A2 + (long)(m0 + lrow) * lda + lcolf + koff : nullptr;
    const int wrow = n0 + lrow;
    const float* Wg = W + (long)(wrow < N ? wrow : 0) * wlda + lcolf + koff;

    float4 ra[4], rw[4];

    float acc[4][4][4];
#pragma unroll
    for (int i = 0; i < 4; i++)
#pragma unroll
        for (int j = 0; j < 4; j++)
#pragma unroll
            for (int e = 0; e < 4; e++) acc[i][j][e] = 0.f;

    const int niter = K / 32;

#pragma unroll
    for (int q = 0; q < 4; q++) {
        ra[q] = *(const float4*)(Ag + q * 4);
        if (Ag2) {
            float4 t = *(const float4*)(Ag2 + q * 4);
            ra[q].x += t.x; ra[q].y += t.y; ra[q].z += t.z; ra[q].w += t.w;
        }
        rw[q] = *(const float4*)(Wg + q * 4);
    }
#pragma unroll
    for (int q = 0; q < 4; q++) {
        unsigned int h0, l0, h1, l1;
        split2(ra[q].x, ra[q].y, h0, l0);
        split2(ra[q].z, ra[q].w, h1, l1);
        SH[0][0][lrow][p0 + 2*q]     = h0;
        SH[0][0][lrow][p0 + 2*q + 1] = h1;
        SH[0][1][lrow][p0 + 2*q]     = l0;
        SH[0][1][lrow][p0 + 2*q + 1] = l1;
        split2(rw[q].x, rw[q].y, h0, l0);
        split2(rw[q].z, rw[q].w, h1, l1);
        SH[0][2][lrow][p0 + 2*q]     = h0;
        SH[0][2][lrow][p0 + 2*q + 1] = h1;
        SH[0][3][lrow][p0 + 2*q]     = l0;
        SH[0][3][lrow][p0 + 2*q + 1] = l1;
    }
    __syncthreads();

    for (int it = 0; it < niter; it++) {
        const int s = it & 1;
        if (it + 1 < niter) {
            const int k0 = (it + 1) * 32;
#pragma unroll
            for (int q = 0; q < 4; q++) {
                ra[q] = *(const float4*)(Ag + k0 + q * 4);
                if (Ag2) {
                    float4 t = *(const float4*)(Ag2 + k0 + q * 4);
                    ra[q].x += t.x; ra[q].y += t.y; ra[q].z += t.z; ra[q].w += t.w;
                }
                rw[q] = *(const float4*)(Wg + k0 + q * 4);
            }
        }

#pragma unroll
        for (int ks = 0; ks < 2; ks++) {
            const int kb = ks * 8 + l4;
            unsigned int bh[4][2], bl[4][2];
#pragma unroll
            for (int j = 0; j < 4; j++) {
                const int r = wn + 8 * j + g;
                bh[j][0] = SH[s][2][r][kb];
                bh[j][1] = SH[s][2][r][kb + 4];
                bl[j][0] = SH[s][3][r][kb];
                bl[j][1] = SH[s][3][r][kb + 4];
            }
#pragma unroll
            for (int i = 0; i < 4; i++) {
                const int r0 = wm + 16 * i + g, r1 = r0 + 8;
                unsigned int ah[4], al[4];
                ah[0] = SH[s][0][r0][kb];     ah[1] = SH[s][0][r1][kb];
                ah[2] = SH[s][0][r0][kb + 4]; ah[3] = SH[s][0][r1][kb + 4];
                al[0] = SH[s][1][r0][kb];     al[1] = SH[s][1][r1][kb];
                al[2] = SH[s][1][r0][kb + 4]; al[3] = SH[s][1][r1][kb + 4];
#pragma unroll
                for (int j = 0; j < 4; j++) mma_bf16(acc[i][j], ah, bh[j]);
#pragma unroll
                for (int j = 0; j < 4; j++) mma_bf16(acc[i][j], ah, bl[j]);
#pragma unroll
                for (int j = 0; j < 4; j++) mma_bf16(acc[i][j], al, bh[j]);
            }
        }

        if (it + 1 < niter) {
            const int s2 = (it + 1) & 1;
#pragma unroll
            for (int q = 0; q < 4; q++) {
                unsigned int h0, l0, h1, l1;
                split2(ra[q].x, ra[q].y, h0, l0);
                split2(ra[q].z, ra[q].w, h1, l1);
                SH[s2][0][lrow][p0 + 2*q]     = h0;
                SH[s2][0][lrow][p0 + 2*q + 1] = h1;
                SH[s2][1][lrow][p0 + 2*q]     = l0;
                SH[s2][1][lrow][p0 + 2*q + 1] = l1;
                split2(rw[q].x, rw[q].y, h0, l0);
                split2(rw[q].z, rw[q].w, h1, l1);
                SH[s2][2][lrow][p0 + 2*q]     = h0;
                SH[s2][2][lrow][p0 + 2*q + 1] = h1;
                SH[s2][3][lrow][p0 + 2*q]     = l0;
                SH[s2][3][lrow][p0 + 2*q + 1] = l1;
            }
        }
        __syncthreads();
    }

    float* Cout = (act == 4 && blockIdx.z == 1) ? C2 : C;
#pragma unroll
    for (int i = 0; i < 4; i++) {
        const int mr0 = m0 + wm + 16 * i + g;
        const int mr1 = mr0 + 8;
#pragma unroll
        for (int j = 0; j < 4; j++) {
            const int n = n0 + wn + 8 * j + 2 * l4;
            if (n < N) {
                float v0 = acc[i][j][0], v1 = acc[i][j][1];
                float v2 = acc[i][j][2], v3 = acc[i][j][3];
                if (act == 3) {
                    atomicAdd(C + (long)mr0 * N + n,     v0);
                    atomicAdd(C + (long)mr0 * N + n + 1, v1);
                    atomicAdd(C + (long)mr1 * N + n,     v2);
                    atomicAdd(C + (long)mr1 * N + n + 1, v3);
                } else {
                    if (act == 0 && bias) {
                        float b0 = bias[n], b1 = bias[n + 1];
                        v0 += b0; v1 += b1; v2 += b0; v3 += b1;
                    }
                    *(float2*)(Cout + (long)mr0 * N + n) = make_float2(v0, v1);
                    *(float2*)(Cout + (long)mr1 * N + n) = make_float2(v2, v3);
                }
            }
        }
    }
}

// ---------------- conv + silu + transpose ----------------
__global__ void conv_t(const float* __restrict__ xz,
                       const float* __restrict__ cw,
                       const float* __restrict__ cb,
                       float* __restrict__ xc, float* __restrict__ xcT)
{
    __shared__ float tile[32][33];
    const int b = blockIdx.z;
    const int t0 = blockIdx.y * 32;
    const int d0 = blockIdx.x * 32;
    const int tx = threadIdx.x, ty = threadIdx.y;
    const int d = d0 + tx;
    const float w0 = cw[d * 2 + 0], w1 = cw[d * 2 + 1], bsv = cb[d];
#pragma unroll
    for (int r = ty; r < 32; r += 8) {
        const int t = t0 + r;
        const long row = (long)(b * L_ + t) * (2 * D_INNER);
        float cur = xz[row + d];
        float prev = (t > 0) ? xz[row - 2 * D_INNER + d] : 0.f;
        float v = prev * w0 + cur * w1 + bsv;
        float sv = v / (1.f + __expf(-v));
        xc[(long)(b * L_ + t) * D_INNER + d] = sv;
        tile[r][tx] = sv;
    }
    __syncthreads();
#pragma unroll
    for (int r = ty; r < 32; r += 8)
        xcT[(long)(b * D_INNER + d0 + r) * L_ + t0 + tx] = tile[tx][r];
}

// ---------------- scan v6: fused dt projection + scan -----------------------
// Block = 128 threads = 4 warps = 8 channels (2/warp), same batch b.
// Stages FULL dbc rows (160 floats, stride 164); lane li<8 of each half
// computes dt for t0+li via 32-FMA dot + softplus; broadcast by shuffle.
#define BCW 164

__global__ __launch_bounds__(128)
void scan6(const float* __restrict__ xcT, const float* __restrict__ dbc,
           const float* __restrict__ dtw, const float* __restrict__ dtb,
           const float* __restrict__ A_log, const float* __restrict__ Dp,
           float* __restrict__ yT)
{
    __shared__ float bc[2][8][BCW];   // full dbc rows: [0:32)=dt-in, [32:96)=B, [96:160)=C
    __shared__ float sdtw[8][32];

    const int tid = threadIdx.x;
    const int w = tid >> 5, lane = tid & 31;
    const int half = lane >> 4, li = lane & 15;
    const int b = blockIdx.x >> 7;
    const int dbase = (blockIdx.x & 127) * 8;
    const int d = dbase + w * 2 + half;

    // stage dtw rows for the block's 8 channels (8*32 = 256 floats = 2/thread)
    {
        const int j0 = tid, j1 = tid + 128;
        sdtw[j0 >> 5][j0 & 31] = dtw[(long)(dbase + (j0 >> 5)) * DT_RANK + (j0 & 31)];
        sdtw[j1 >> 5][j1 & 31] = dtw[(long)(dbase + (j1 >> 5)) * DT_RANK + (j1 & 31)];
    }

    float Ar[4];
#pragma unroll
    for (int j = 0; j < 4; j++)
        Ar[j] = -__expf(A_log[d * D_STATE + 4 * li + j]);
    const float Dd = Dp[d];
    const float dtbias = dtb[d];
    const int chloc = w * 2 + half;

    const float* xp = xcT + ((long)b * D_INNER + d) * L_;
    const float* bcsrc = dbc + (long)b * L_ * 160;
    float* yp = yT + ((long)b * D_INNER + d) * L_;

    // stage chunk 0: 8 rows x 160 floats = 320 float4 over 128 threads
    {
#pragma unroll
        for (int v = 0; v < 3; v++) {
            const int j = tid + v * 128;
            if (j < 320) {
                const int r = j / 40, c = (j % 40) * 4;
                *(float4*)&bc[0][r][c] = *(const float4*)(bcsrc + (long)r * 160 + c);
            }
        }
    }
    __syncthreads();

    float h0 = 0.f, h1 = 0.f, h2 = 0.f, h3 = 0.f;
    for (int c = 0; c < L_ / 8; c++) {
        const int s = c & 1;
        const int t0 = c * 8;

        float4 stg[3];
        int rs[3], cs[3];
        const bool more = (c + 1 < L_ / 8);
        if (more) {
            const int tn = t0 + 8;
#pragma unroll
            for (int v = 0; v < 3; v++) {
                const int j = tid + v * 128;
                rs[v] = j / 40; cs[v] = (j % 40) * 4;
                if (j < 320)
                    stg[v] = *(const float4*)(bcsrc + (long)(tn + rs[v]) * 160 + cs[v]);
            }
        }

        // fused dt: lane li<8 computes dt for t = t0+li of its channel
        float dtval = 0.f;
        if (li < 8) {
            float sacc = dtbias;
#pragma unroll
            for (int k = 0; k < 32; k += 4) {
                sacc = fmaf(sdtw[chloc][k],     bc[s][li][k],     sacc);
                sacc = fmaf(sdtw[chloc][k + 1], bc[s][li][k + 1], sacc);
                sacc = fmaf(sdtw[chloc][k + 2], bc[s][li][k + 2], sacc);
                sacc = fmaf(sdtw[chloc][k + 3], bc[s][li][k + 3], sacc);
            }
            dtval = softplus_f(sacc);
        }

        float xa[8], ya[8];
        *(float4*)&xa[0] = *(const float4*)(xp + t0);
        *(float4*)&xa[4] = *(const float4*)(xp + t0 + 4);

#pragma unroll
        for (int q = 0; q < 8; q++) {
            const float dtv = __shfl_sync(0xffffffffu, dtval, half * 16 + q);
            const float4 Bv = *(const float4*)&bc[s][q][32 + 4 * li];
            const float4 Cv = *(const float4*)&bc[s][q][96 + 4 * li];
            const float xv = xa[q];
            const float u = dtv * xv;
            h0 = fmaf(h0, __expf(dtv * Ar[0]), u * Bv.x);
            h1 = fmaf(h1, __expf(dtv * Ar[1]), u * Bv.y);
            h2 = fmaf(h2, __expf(dtv * Ar[2]), u * Bv.z);
            h3 = fmaf(h3, __expf(dtv * Ar[3]), u * Bv.w);
            float p = h0 * Cv.x + h1 * Cv.y + h2 * Cv.z + h3 * Cv.w;
#pragma unroll
            for (int o = 8; o; o >>= 1) p += __shfl_xor_sync(0xffffffffu, p, o);
            ya[q] = p + xv * Dd;
        }
        if (li == 0) {
            *(float4*)(yp + t0)     = *(const float4*)&ya[0];
            *(float4*)(yp + t0 + 4) = *(const float4*)&ya[4];
        }

        if (more) {
#pragma unroll
            for (int v = 0; v < 3; v++) {
                const int j = tid + v * 128;
                if (j < 320)
                    *(float4*)&bc[s ^ 1][rs[v]][cs[v]] = stg[v];
            }
        }
        __syncthreads();
    }
}

// ---------------- gated transpose ----------------
__global__ void gate_t(const float* __restrict__ yT, const float* __restrict__ xz,
                       float* __restrict__ y)
{
    __shared__ float tile[32][33];
    const int b = blockIdx.z;
    const int t0 = blockIdx.y * 32;
    const int d0 = blockIdx.x * 32;
    const int tx = threadIdx.x, ty = threadIdx.y;
#pragma unroll
    for (int r = ty; r < 32; r += 8)
        tile[r][tx] = yT[(long)(b * D_INNER + d0 + r) * L_ + t0 + tx];
    __syncthreads();
#pragma unroll
    for (int r = ty; r < 32; r += 8) {
        const int t = t0 + r, d = d0 + tx;
        const float zv = xz[(long)(b * L_ + t) * (2 * D_INNER) + D_INNER + d];
        y[(long)(b * L_ + t) * D_INNER + d] = tile[tx][r] * (zv / (1.f + __expf(-zv)));
    }
}

// ---------------- final FC ----------------
__global__ void fc_kernel(const float* __restrict__ h, const float* __restrict__ h2,
                          const float* __restrict__ fc_w,
                          const float* __restrict__ fc_b, float* __restrict__ out)
{
    const int w = threadIdx.x >> 5;
    const int lane = threadIdx.x & 31;
    if (w >= B_ * N_CLASSES) return;
    const int b = w / N_CLASSES, c = w % N_CLASSES;
    const long off = (long)(b * L_ + (L_ - 1)) * D_MODEL;
    float s = 0.f;
    for (int k = lane; k < D_MODEL; k += 32)
        s += (h[off + k] + h2[off + k]) * fc_w[c * D_MODEL + k];
#pragma unroll
    for (int o = 16; o; o >>= 1) s += __shfl_xor_sync(0xffffffffu, s, o);
    if (lane == 0) out[b * N_CLASSES + c] = s + fc_b[c];
}

// ---------------- launch ----------------
extern "C" void kernel_launch(void* const* d_in, const int* in_sizes, int n_in,
                              void* d_out, int out_size)
{
    const float* x        = (const float*)d_in[0];
    const float* exp_w    = (const float*)d_in[1];
    const float* exp_b    = (const float*)d_in[2];
    const float* in_w     = (const float*)d_in[3];
    const float* conv_w   = (const float*)d_in[4];
    const float* conv_b   = (const float*)d_in[5];
    const float* xproj_w  = (const float*)d_in[6];
    const float* dtproj_w = (const float*)d_in[7];
    const float* dtproj_b = (const float*)d_in[8];
    const float* A_log    = (const float*)d_in[9];
    const float* Dp       = (const float*)d_in[10];
    const float* out_w    = (const float*)d_in[11];
    const float* fc_w     = (const float*)d_in[12];
    const float* fc_b     = (const float*)d_in[13];
    float* out = (float*)d_out;

    float *ph, *ph2, *pxz, *pxc, *pdbc, *py, *pxcT, *pyT;
    cudaGetSymbolAddress((void**)&ph,   g_h);
    cudaGetSymbolAddress((void**)&ph2,  g_h2);
    cudaGetSymbolAddress((void**)&pxz,  g_xz);
    cudaGetSymbolAddress((void**)&pxc,  g_xc);
    cudaGetSymbolAddress((void**)&pdbc, g_dbc);
    cudaGetSymbolAddress((void**)&py,   g_y);
    cudaGetSymbolAddress((void**)&pxcT, g_xcT);
    cudaGetSymbolAddress((void**)&pyT,  g_yT);

    const dim3 tgrid(32, 32, 4), tblk(32, 8);

    // embed: h = x @ exp_w^T + exp_b   (4096 x 512, K=128)
    gemm3b<0><<<dim3(D_MODEL / 128, ML / 128), 256>>>(
        x, nullptr, exp_w, exp_b, ph, nullptr, ML, D_MODEL, D_IN, D_IN, D_IN, 0);

    for (int l = 0; l < N_LAYERS; l++) {
        const float* in_w_l   = in_w     + (long)l * 2 * D_INNER * D_MODEL;
        const float* conv_w_l = conv_w   + (long)l * D_INNER * D_CONV;
        const float* conv_b_l = conv_b   + (long)l * D_INNER;
        const float* xproj_l  = xproj_w  + (long)l * 160 * D_INNER;
        const float* dtw_l    = dtproj_w + (long)l * D_INNER * DT_RANK;
        const float* dtb_l    = dtproj_b + (long)l * D_INNER;
        const float* Alog_l   = A_log    + (long)l * D_INNER * D_STATE;
        const float* Dp_l     = Dp       + (long)l * D_INNER;
        const float* out_w_l  = out_w    + (long)l * D_MODEL * D_INNER;

        // xz = (h [+h2]) @ in_w^T   (4096 x 2048, K=512)
        gemm3b<1><<<dim3(2 * D_INNER / 128, ML / 128), 256>>>(
            ph, (l > 0) ? ph2 : nullptr, in_w_l, nullptr, pxz, nullptr,
            ML, 2 * D_INNER, D_MODEL, D_MODEL, D_MODEL, 0);
        // conv + silu + transpose -> xc, xcT
        conv_t<<<tgrid, tblk>>>(pxz, conv_w_l, conv_b_l, pxc, pxcT);
        // dbc = xc @ xproj^T  (4096 x 160, K=1024) — split-K x4, atomic accumulate
        cudaMemsetAsync(pdbc, 0, (size_t)ML * 160 * sizeof(float));
        gemm3b<2><<<dim3(2, ML / 128, 4), 256>>>(
            pxc, nullptr, xproj_l, nullptr, pdbc, nullptr,
            ML, 160, 256, D_INNER, D_INNER, 3);
        // fused dt-projection + selective scan -> yT (ungated)
        scan6<<<(B_ * D_INNER) / 8, 128>>>(pxcT, pdbc, dtw_l, dtb_l, Alog_l, Dp_l, pyT);
        // gate + transpose back -> y [t][d]
        gate_t<<<tgrid, tblk>>>(pyT, pxz, py);
        // h = y @ out_w^T  (4096 x 512, K=1024) — split-K x2, per-slice buffers
        gemm3b<4><<<dim3(D_MODEL / 128, ML / 128, 2), 256>>>(
            py, nullptr, out_w_l, nullptr, ph, ph2,
            ML, D_MODEL, 512, D_INNER, D_INNER, 4);
    }

    fc_kernel<<<1, 384>>>(ph, ph2, fc_w, fc_b, out);
}